// round 14
// baseline (speedup 1.0000x reference)
#include <cuda_runtime.h>

// Problem constants
#define NC 52
#define RT 64                      // NR*NT, contiguous per (ray,s,ch)
#define NS 128
#define NRAYS 64
#define NCRT (NC*RT)               // 3328 channels per ray
#define X_S_STRIDE (3*NCRT)        // 9984 floats per s-step in x
#define Z_S_STRIDE (2*NCRT)        // 6656 floats per s-step in z_vals
#define N_ELEMS (NRAYS*NCRT)       // 212,992 complex outputs

#define BLK 128                    // 64 channels x 2 half-scans
#define CH_PER_BLK 64
#define HALF_NS 64

// Split-scan: the factorized recurrence (E = prod exp(-a), phi = wrapped sum
// theta) is associative, so each channel's 128-step scan splits across TWO
// threads (half A: s=0..63, half B: s=64..127 with identity prefix), composed
// as acc = acc_A + E_A*exp(-i*phi_A)*acc_B via 1KB smem + one barrier.
// This doubles threads to 425,984 -> 2048/SM resident (64 warps, was 45),
// the one lever R8-R13 never moved. launch_bounds(128,16) pins regs <= 32.
__global__ void __launch_bounds__(BLK, 16) renderer_kernel(
    const float* __restrict__ x,
    const float* __restrict__ z_vals,
    const float* __restrict__ fc_vec,
    float* __restrict__ out,
    int out_mode)
{
    __shared__ float sE[CH_PER_BLK], sPhi[CH_PER_BLK];
    __shared__ float sAr[CH_PER_BLK], sAi[CH_PER_BLK];

    const int tid  = threadIdx.x;
    const int ch   = tid & (CH_PER_BLK - 1);       // channel within block
    const int half = tid >> 6;                     // 0: s=0..63, 1: s=64..127
    const int gch  = blockIdx.x * CH_PER_BLK + ch; // global channel
    const int rt   = gch & (RT - 1);
    const int c    = (gch >> 6) % NC;
    const int ray  = gch / NCRT;

    const float C_LIGHT = 299792458.0f;
    const float PI_F    = 3.14159265358979f;

    const float fc = __ldg(&fc_vec[NC + c]);       // fc_down
    const float wavenumber = 2.0f * PI_F * fc * 1.0e9f / C_LIGHT;
    const float ampk       = C_LIGHT / (fc * 1.0e9f * 4.0f * PI_F);

    const float* xb = x      + (size_t)ray * ((size_t)NS * X_S_STRIDE) + c * RT + rt;
    const float* zb = z_vals + (size_t)ray * ((size_t)NS * Z_S_STRIDE) + c * RT + rt;

    const float INV_2PI   = 0.15915494309189535f;
    const float TWO_PI_HI = 6.28318548202514648f;  // float(2*pi)
    const float TWO_PI_LO = -1.7484555e-7f;        // 2*pi - TWO_PI_HI

    const int s0 = half * HALF_NS;

    float E = 1.0f, phi = 0.0f;                    // local prefix (identity)
    float acc_re = 0.0f, acc_im = 0.0f;
    float z_cur = __ldcs(zb + s0 * Z_S_STRIDE);

    #pragma unroll 4
    for (int i = 0; i < HALF_NS; ++i) {
        const int s = s0 + i;
        const float* xp = xb + s * X_S_STRIDE;
        const float x_re  = __ldcs(xp);
        const float x_im  = __ldcs(xp + NCRT);
        const float a_raw = __ldcs(xp + 2 * NCRT);

        const float e = __expf(-a_raw);            // (1 - alpha)

        if (s != 0) {                              // exclusive prefix at s=0 is 0
            float sn, cs;
            __sincosf(phi, &sn, &cs);              // local T phase = cs - i*sn
            const float g = __fdividef(ampk * E * (1.0f - e), z_cur);
            acc_re = fmaf(g, fmaf(x_im, sn,  x_re * cs), acc_re);
            acc_im = fmaf(g, fmaf(x_im, cs, -x_re * sn), acc_im);
        }

        if (s != NS - 1) {                         // s=127 factor never consumed
            const float z_next = __ldcs(zb + (s + 1) * Z_S_STRIDE);
            E *= e;
            const float th = wavenumber * (z_next - z_cur);
            float p = phi + th;
            const float n = rintf(p * INV_2PI);
            p   = fmaf(-n, TWO_PI_HI, p);
            phi = fmaf(-n, TWO_PI_LO, p);
            z_cur = z_next;
        }
    }

    // Compose: out = acc_A + E_A * exp(-i*phi_A) * acc_B
    if (half == 0) {
        sE[ch]  = E;   sPhi[ch] = phi;
        sAr[ch] = acc_re; sAi[ch] = acc_im;
    }
    __syncthreads();
    if (half == 1) {
        const float Ea = sE[ch];
        float sn, cs;
        __sincosf(sPhi[ch], &sn, &cs);
        const float tre = Ea * cs;                 // T_A = tre + i*tim
        const float tim = -Ea * sn;
        const float fre = sAr[ch] + tre * acc_re - tim * acc_im;
        const float fim = sAi[ch] + tre * acc_im + tim * acc_re;

        if (out_mode == 0) {
            out[gch] = fre;                        // real part only
        } else {
            out[gch]           = fre;              // planar: re block | im block
            out[gch + N_ELEMS] = fim;
        }
    }
}

extern "C" void kernel_launch(void* const* d_in, const int* in_sizes, int n_in,
                              void* d_out, int out_size)
{
    // Dispatch inputs by element count — robust to metadata ordering.
    const float* x      = nullptr;
    const float* z_vals = nullptr;
    const float* fc_vec = nullptr;
    const long long X_N  = (long long)NRAYS * NS * 3 * NCRT;   // 81,788,928
    const long long Z_N  = (long long)NRAYS * NS * 2 * NCRT;   // 54,525,952
    const long long FC_N = 2 * NC;                             // 104
    for (int i = 0; i < n_in; ++i) {
        const long long n = (long long)in_sizes[i];
        if      (n == X_N)  x      = (const float*)d_in[i];
        else if (n == Z_N)  z_vals = (const float*)d_in[i];
        else if (n == FC_N) fc_vec = (const float*)d_in[i];
    }
    if (!x && n_in >= 1)      x      = (const float*)d_in[0];
    if (!z_vals && n_in >= 2) z_vals = (const float*)d_in[1];
    if (!fc_vec && n_in >= 3) fc_vec = (const float*)d_in[2];

    // Output: N_ELEMS floats -> real-only; 2*N_ELEMS -> planar [re | im]
    const int out_mode = (out_size == N_ELEMS) ? 0 : 1;

    const int grid = N_ELEMS / CH_PER_BLK;          // 3328 blocks of 128
    renderer_kernel<<<grid, BLK>>>(x, z_vals, fc_vec, (float*)d_out, out_mode);
}

// round 15
// speedup vs baseline: 1.1079x; 1.1079x over previous
#include <cuda_runtime.h>

// Problem constants
#define NC 52
#define RT 64                      // NR*NT, contiguous per (ray,s,ch)
#define NS 128
#define NRAYS 64
#define NCRT (NC*RT)               // 3328 channels per ray
#define X_S_STRIDE (3*NCRT)        // 9984 floats per s-step in x
#define Z_S_STRIDE (2*NCRT)        // 6656 floats per s-step in z_vals
#define N_ELEMS (NRAYS*NCRT)       // 212,992 complex outputs

// Best-measured structure (R10, 72.2us) + __ldcs streaming policy.
// Factorized recurrence: (1-alpha) = exp(-a_raw) exactly, so
//   T_<s = (prod_j exp(-a_j)) * exp(-i * wrapped_sum theta_j)
// (1e-10 epsilon dropped: <= 4e-6 rel effect). 2-ahead rotating register
// prefetch; block=128, grid=1664, 39 regs -> 12 resident blocks, single wave.
// R8-R14 established the pattern ceiling ~6.05 TB/s; this kernel runs ~0.4%
// off the resulting 71.9us floor.
__global__ void __launch_bounds__(128, 12) renderer_kernel(
    const float* __restrict__ x,
    const float* __restrict__ z_vals,
    const float* __restrict__ fc_vec,
    float* __restrict__ out,
    int out_mode)
{
    const int gid = blockIdx.x * blockDim.x + threadIdx.x;
    const int rt  = gid & (RT - 1);
    const int c   = (gid >> 6) % NC;
    const int ray = gid / NCRT;

    const float C_LIGHT = 299792458.0f;
    const float PI_F    = 3.14159265358979f;

    const float fc = __ldg(&fc_vec[NC + c]);                 // fc_down
    const float wavenumber = 2.0f * PI_F * fc * 1.0e9f / C_LIGHT;
    const float ampk       = C_LIGHT / (fc * 1.0e9f * 4.0f * PI_F);

    const float* xb = x      + (size_t)ray * ((size_t)NS * X_S_STRIDE) + c * RT + rt;
    const float* zb = z_vals + (size_t)ray * ((size_t)NS * Z_S_STRIDE) + c * RT + rt;

    const float INV_2PI   = 0.15915494309189535f;
    const float TWO_PI_HI = 6.28318548202514648f;   // float(2*pi)
    const float TWO_PI_LO = -1.7484555e-7f;         // 2*pi - TWO_PI_HI

    float E;                          // prod exp(-a_j), j < s
    float phi;                        // wrapped sum theta_j, j < s
    float acc_re = 0.0f, acc_im = 0.0f;
    float z_cur;

    // ---- s = 0 (peeled): contribution is zero; seed E and phi.
    {
        const float z0 = __ldcs(zb);
        const float z1 = __ldcs(zb + Z_S_STRIDE);
        const float a0 = __ldcs(xb + 2 * NCRT);
        E = __expf(-a0);
        const float th = wavenumber * (z1 - z0);
        const float n = rintf(th * INV_2PI);
        phi = fmaf(-n, TWO_PI_HI, th);
        phi = fmaf(-n, TWO_PI_LO, phi);
        z_cur = z1;
    }

    // Two rotating prefetch sets; set b holds {x3[t], z[t+1]} for iteration t.
    float px[2], pxi[2], pa[2], pz[2];
    {
        const int xo1 = 1 * X_S_STRIDE, xo2 = 2 * X_S_STRIDE;
        px[0]  = __ldcs(xb + xo1);
        pxi[0] = __ldcs(xb + xo1 + NCRT);
        pa[0]  = __ldcs(xb + xo1 + 2 * NCRT);
        pz[0]  = __ldcs(zb + 2 * Z_S_STRIDE);
        px[1]  = __ldcs(xb + xo2);
        pxi[1] = __ldcs(xb + xo2 + NCRT);
        pa[1]  = __ldcs(xb + xo2 + 2 * NCRT);
        pz[1]  = __ldcs(zb + 3 * Z_S_STRIDE);
    }

    // ---- s = 1 .. 124: steady state, 2-ahead prefetch.
    #pragma unroll 2
    for (int s = 1; s <= 124; ++s) {
        const int b = (s - 1) & 1;
        const float x_re   = px[b];
        const float x_im   = pxi[b];
        const float a_raw  = pa[b];
        const float z_next = pz[b];

        // prefetch iteration s+2 into the freed set (z index s+3 <= 127)
        const int xo = (s + 2) * X_S_STRIDE;
        px[b]  = __ldcs(xb + xo);
        pxi[b] = __ldcs(xb + xo + NCRT);
        pa[b]  = __ldcs(xb + xo + 2 * NCRT);
        pz[b]  = __ldcs(zb + (s + 3) * Z_S_STRIDE);

        // contribution uses CURRENT (exclusive) E, phi
        float sn, cs;
        __sincosf(phi, &sn, &cs);                 // T phase = cs - i*sn
        const float e     = __expf(-a_raw);       // (1 - alpha)
        const float alpha = 1.0f - e;
        const float g     = __fdividef(ampk * E * alpha, z_cur);

        acc_re = fmaf(g, fmaf(x_im, sn,  x_re * cs), acc_re);
        acc_im = fmaf(g, fmaf(x_im, cs, -x_re * sn), acc_im);

        // advance magnitude and wrapped phase
        E *= e;
        const float th = wavenumber * (z_next - z_cur);
        float p = phi + th;
        const float n = rintf(p * INV_2PI);
        p   = fmaf(-n, TWO_PI_HI, p);
        phi = fmaf(-n, TWO_PI_LO, p);
        z_cur = z_next;
    }

    // ---- s = 125 (b=0): consume; prefetch x[127] only (its z is unused).
    {
        const float x_re = px[0], x_im = pxi[0], a_raw = pa[0], z_next = pz[0];
        const int xo = 127 * X_S_STRIDE;
        px[0]  = __ldcs(xb + xo);
        pxi[0] = __ldcs(xb + xo + NCRT);
        pa[0]  = __ldcs(xb + xo + 2 * NCRT);

        float sn, cs;
        __sincosf(phi, &sn, &cs);
        const float e     = __expf(-a_raw);
        const float alpha = 1.0f - e;
        const float g     = __fdividef(ampk * E * alpha, z_cur);
        acc_re = fmaf(g, fmaf(x_im, sn,  x_re * cs), acc_re);
        acc_im = fmaf(g, fmaf(x_im, cs, -x_re * sn), acc_im);

        E *= e;
        const float th = wavenumber * (z_next - z_cur);
        float p = phi + th;
        const float n = rintf(p * INV_2PI);
        p   = fmaf(-n, TWO_PI_HI, p);
        phi = fmaf(-n, TWO_PI_LO, p);
        z_cur = z_next;
    }

    // ---- s = 126 (b=1): consume; no prefetch.
    {
        const float x_re = px[1], x_im = pxi[1], a_raw = pa[1], z_next = pz[1];

        float sn, cs;
        __sincosf(phi, &sn, &cs);
        const float e     = __expf(-a_raw);
        const float alpha = 1.0f - e;
        const float g     = __fdividef(ampk * E * alpha, z_cur);
        acc_re = fmaf(g, fmaf(x_im, sn,  x_re * cs), acc_re);
        acc_im = fmaf(g, fmaf(x_im, cs, -x_re * sn), acc_im);

        E *= e;
        const float th = wavenumber * (z_next - z_cur);
        float p = phi + th;
        const float n = rintf(p * INV_2PI);
        p   = fmaf(-n, TWO_PI_HI, p);
        phi = fmaf(-n, TWO_PI_LO, p);
        z_cur = z_next;
    }

    // ---- s = 127 (peeled): contribution only; its factor is never consumed.
    {
        const float x_re = px[0], x_im = pxi[0], a_raw = pa[0];
        float sn, cs;
        __sincosf(phi, &sn, &cs);
        const float e     = __expf(-a_raw);
        const float alpha = 1.0f - e;
        const float g     = __fdividef(ampk * E * alpha, z_cur);
        acc_re = fmaf(g, fmaf(x_im, sn,  x_re * cs), acc_re);
        acc_im = fmaf(g, fmaf(x_im, cs, -x_re * sn), acc_im);
    }

    if (out_mode == 0) {
        out[gid] = acc_re;                      // real part only
    } else {
        out[gid]           = acc_re;            // planar: re block | im block
        out[gid + N_ELEMS] = acc_im;
    }
}

extern "C" void kernel_launch(void* const* d_in, const int* in_sizes, int n_in,
                              void* d_out, int out_size)
{
    // Dispatch inputs by element count — robust to metadata ordering.
    const float* x      = nullptr;
    const float* z_vals = nullptr;
    const float* fc_vec = nullptr;
    const long long X_N  = (long long)NRAYS * NS * 3 * NCRT;   // 81,788,928
    const long long Z_N  = (long long)NRAYS * NS * 2 * NCRT;   // 54,525,952
    const long long FC_N = 2 * NC;                             // 104
    for (int i = 0; i < n_in; ++i) {
        const long long n = (long long)in_sizes[i];
        if      (n == X_N)  x      = (const float*)d_in[i];
        else if (n == Z_N)  z_vals = (const float*)d_in[i];
        else if (n == FC_N) fc_vec = (const float*)d_in[i];
    }
    if (!x && n_in >= 1)      x      = (const float*)d_in[0];
    if (!z_vals && n_in >= 2) z_vals = (const float*)d_in[1];
    if (!fc_vec && n_in >= 3) fc_vec = (const float*)d_in[2];

    // Output: N_ELEMS floats -> real-only; 2*N_ELEMS -> planar [re | im]
    const int out_mode = (out_size == N_ELEMS) ? 0 : 1;

    const int block = 128;
    const int grid  = N_ELEMS / block;              // 1664 blocks, single wave
    renderer_kernel<<<grid, block>>>(x, z_vals, fc_vec, (float*)d_out, out_mode);
}